// round 10
// baseline (speedup 1.0000x reference)
#include <cuda_runtime.h>
#include <cuda_fp16.h>
#include <stdint.h>

#define BATCH 4
#define SEQ   2048
#define DM    1024
typedef __half fp16;

// ---------------- scratch (__device__ globals; no allocation) ----------------
__device__ fp16 g_x16[(size_t)BATCH*SEQ*DM];      // x single fp16
__device__ fp16 g_wt[(size_t)3*DM*DM];            // W^T single fp16: [3*DM][DM]
__device__ float g_bias[3*DM];
__device__ fp16 g_qkv[(size_t)BATCH*SEQ*3*DM];    // [B*S][3DM]: q | k | v
__device__ fp16 g_vt[(size_t)BATCH*DM*SEQ];       // V^T
__device__ float g_s[(size_t)BATCH*SEQ*SEQ];      // scores fp32
__device__ fp16 g_p[(size_t)BATCH*SEQ*SEQ];       // attn probs fp16

// ---------------- helpers ----------------
__device__ __forceinline__ uint32_t s2u(const void* p) {
    uint32_t a;
    asm("{ .reg .u64 t; cvta.to.shared.u64 t, %1; cvt.u32.u64 %0, t; }" : "=r"(a) : "l"(p));
    return a;
}
__device__ __forceinline__ void ldsm4(uint32_t* r, uint32_t addr) {
    asm volatile("ldmatrix.sync.aligned.m8n8.x4.shared.b16 {%0,%1,%2,%3}, [%4];"
                 : "=r"(r[0]), "=r"(r[1]), "=r"(r[2]), "=r"(r[3]) : "r"(addr));
}
__device__ __forceinline__ void mma16816(float* d, const uint32_t* a, uint32_t b0, uint32_t b1) {
    asm volatile(
        "mma.sync.aligned.m16n8k16.row.col.f32.f16.f16.f32 "
        "{%0,%1,%2,%3}, {%4,%5,%6,%7}, {%8,%9}, {%0,%1,%2,%3};"
        : "+f"(d[0]), "+f"(d[1]), "+f"(d[2]), "+f"(d[3])
        : "r"(a[0]), "r"(a[1]), "r"(a[2]), "r"(a[3]), "r"(b0), "r"(b1));
}

// ---------------- HMMA GEMM: C = scale*(A@B^T) [+bias], single fp16 product ----------------
// A [M,K] stride lda, B [N,K] stride ldb, out fp32 Cf OR fp16 Chi (stride ldc).
// CTA tile 128x256, BK=64, 256 threads (8 warps, warp grid 2m x 4n, warp tile 64x64),
// 3 stages, 1 CTA/SM (high-register). SMSP-partner warps rotate k-step phase.
#define BK      64
#define TILE_A  16384                    // 128 rows * 128B
#define TILE_Bb 32768                    // 256 rows * 128B
#define STAGE_B (TILE_A + TILE_Bb)       // 48 KB
#define NSTG    3
#define GSMEM   (NSTG * STAGE_B)         // 144 KB

__global__ __launch_bounds__(256, 1) void gemmw(
    const fp16* __restrict__ A, const fp16* __restrict__ B,
    const float* __restrict__ bias, float scale,
    float* __restrict__ Cf, fp16* __restrict__ Chi,
    int K, int lda, int ldb, int ldc,
    size_t sA, size_t sB, size_t sC)
{
    extern __shared__ char smem[];
    const uint32_t sb = s2u(smem);
    const int tid = threadIdx.x;
    const int wid = tid >> 5, lane = tid & 31;
    const int wm = wid & 1, wn = wid >> 1;           // warp grid 2 (m) x 4 (n)
    const int m0 = blockIdx.y * 128, n0 = blockIdx.x * 256;
    const int NC = K / BK;
    const int rot = (wid >> 2) << 1;                 // SMSP partners offset by 2 k-steps

    const fp16* bA = A + (size_t)blockIdx.z * sA + (size_t)m0 * lda;
    const fp16* bB = B + (size_t)blockIdx.z * sB + (size_t)n0 * ldb;

    auto load_chunk = [&](int c) {
        const uint32_t stg = sb + (uint32_t)(c % NSTG) * STAGE_B;
        const int k0 = c * BK;
        #pragma unroll
        for (int i = 0; i < 12; i++) {
            const bool isA = (i < 4);
            const int sub = isA ? (tid + i * 256) : (tid + (i - 4) * 256);
            const int row = sub >> 3, col = sub & 7;    // A: 128 rows, B: 256 rows x 8 16B-cols
            const fp16* src = (isA ? bA : bB) + (size_t)row * (isA ? lda : ldb) + k0 + col * 8;
            uint32_t off = (uint32_t)(row * 128 + col * 16);
            uint32_t dst = stg + (isA ? 0u : (uint32_t)TILE_A) + (off ^ ((off >> 3) & 0x70));
            asm volatile("cp.async.cg.shared.global [%0], [%1], 16;" :: "r"(dst), "l"(src) : "memory");
        }
        asm volatile("cp.async.commit_group;" ::: "memory");
    };

    // per-lane ldmatrix addressing (SW128 rows of 128B)
    const int rlane = (lane & 7) + ((lane >> 3) & 1) * 8;
    const uint32_t xlane = (uint32_t)((rlane & 7) * 16);
    const uint32_t kbl = (uint32_t)((lane >> 4) * 16);
    uint32_t aoff[4], boff[4], kx[4];
    #pragma unroll
    for (int mf = 0; mf < 4; mf++) aoff[mf] = (uint32_t)((wm * 64 + mf * 16 + rlane) << 7);
    #pragma unroll
    for (int g = 0; g < 4; g++) boff[g] = (uint32_t)((wn * 64 + g * 16 + rlane) << 7);
    #pragma unroll
    for (int ks = 0; ks < 4; ks++) kx[ks] = ((uint32_t)(ks * 32) + kbl) ^ xlane;

    float acc[4][8][4] = {};

    load_chunk(0);
    if (NC > 1) load_chunk(1);

    for (int c = 0; c < NC; ++c) {
        if (c + 2 < NC) asm volatile("cp.async.wait_group 1;" ::: "memory");
        else            asm volatile("cp.async.wait_group 0;" ::: "memory");
        __syncthreads();                       // chunk c visible; oldest stage free
        if (c + 2 < NC) load_chunk(c + 2);

        const uint32_t stg = sb + (uint32_t)(c % NSTG) * STAGE_B;
        const uint32_t sA_ = stg, sB_ = stg + TILE_A;

        #pragma unroll
        for (int ks = 0; ks < 4; ks++) {
            const uint32_t kk = kx[(ks + rot) & 3];
            uint32_t ah[4][4], bf[8][2];
            #pragma unroll
            for (int mf = 0; mf < 4; mf++)
                ldsm4(ah[mf], sA_ + aoff[mf] + kk);
            #pragma unroll
            for (int g = 0; g < 4; g++) {
                uint32_t t[4];
                ldsm4(t, sB_ + boff[g] + kk);
                bf[2*g][0] = t[0]; bf[2*g+1][0] = t[1];
                bf[2*g][1] = t[2]; bf[2*g+1][1] = t[3];
            }
            #pragma unroll
            for (int mf = 0; mf < 4; mf++)
                #pragma unroll
                for (int nf = 0; nf < 8; nf++)
                    mma16816(acc[mf][nf], ah[mf], bf[nf][0], bf[nf][1]);
        }
    }

    // ---------------- epilogue ----------------
    const size_t cb = (size_t)blockIdx.z * sC;
    #pragma unroll
    for (int mf = 0; mf < 4; mf++) {
        #pragma unroll
        for (int nf = 0; nf < 8; nf++) {
            const int m = m0 + wm * 64 + mf * 16 + (lane >> 2);
            const int n = n0 + wn * 64 + nf * 8 + 2 * (lane & 3);
            const float b0 = bias ? bias[n] : 0.f;
            const float b1 = bias ? bias[n + 1] : 0.f;
            float v00 = acc[mf][nf][0] * scale + b0;
            float v01 = acc[mf][nf][1] * scale + b1;
            float v10 = acc[mf][nf][2] * scale + b0;
            float v11 = acc[mf][nf][3] * scale + b1;
            if (Cf) {
                float2 o0 = {v00, v01}, o1 = {v10, v11};
                *reinterpret_cast<float2*>(Cf + cb + (size_t)m * ldc + n)       = o0;
                *reinterpret_cast<float2*>(Cf + cb + (size_t)(m + 8) * ldc + n) = o1;
            } else {
                __half2 ph0 = {__float2half(v00), __float2half(v01)};
                __half2 ph1 = {__float2half(v10), __float2half(v11)};
                *reinterpret_cast<__half2*>(Chi + cb + (size_t)m * ldc + n)       = ph0;
                *reinterpret_cast<__half2*>(Chi + cb + (size_t)(m + 8) * ldc + n) = ph1;
            }
        }
    }
}

// ---------------- aux kernels ----------------
__global__ __launch_bounds__(256) void conv_f16(const float* __restrict__ in,
                                                fp16* __restrict__ o, int n4)
{
    int i = blockIdx.x * 256 + threadIdx.x;
    if (i >= n4) return;
    float4 v = reinterpret_cast<const float4*>(in)[i];
    __align__(8) fp16 h[4];
    h[0] = __float2half(v.x); h[1] = __float2half(v.y);
    h[2] = __float2half(v.z); h[3] = __float2half(v.w);
    reinterpret_cast<uint2*>(o)[i] = *reinterpret_cast<uint2*>(h);
}

__global__ void concat_bias(const float* a, const float* b, const float* c, float* o)
{
    int i = blockIdx.x * 256 + threadIdx.x;
    if (i < DM)            o[i] = a[i];
    else if (i < 2 * DM)   o[i] = b[i - DM];
    else if (i < 3 * DM)   o[i] = c[i - 2 * DM];
}

// W [K=DM, N=DM] fp32 -> wt fp16 [N, K] (transposed), z selects Wq/Wk/Wv
__global__ void transpose_w_f16(const float* __restrict__ Wq, const float* __restrict__ Wk,
                                const float* __restrict__ Wv, fp16* __restrict__ wt)
{
    __shared__ float t[32][33];
    const float* W = blockIdx.z == 0 ? Wq : blockIdx.z == 1 ? Wk : Wv;
    fp16* o = wt + (size_t)blockIdx.z * DM * DM;
    const int n0 = blockIdx.x * 32, k0 = blockIdx.y * 32;
    const int tx = threadIdx.x, ty = threadIdx.y;
    #pragma unroll
    for (int r = 0; r < 4; r++)
        t[ty + 8 * r][tx] = W[(size_t)(k0 + ty + 8 * r) * DM + n0 + tx];
    __syncthreads();
    #pragma unroll
    for (int r = 0; r < 4; r++)
        o[(size_t)(n0 + ty + 8 * r) * DM + k0 + tx] = __float2half(t[tx][ty + 8 * r]);
}

// V slice of [B][SEQ][3*DM] (fp16, stride ldin) -> [B][DM][SEQ] fp16 transpose
__global__ void transpose_f16(const fp16* __restrict__ in, fp16* __restrict__ out, int ldin)
{
    __shared__ fp16 t[32][33];
    const size_t ib = (size_t)blockIdx.z * SEQ * ldin;
    const size_t ob = (size_t)blockIdx.z * DM * SEQ;
    const int s0 = blockIdx.y * 32, d0 = blockIdx.x * 32;
    const int tx = threadIdx.x, ty = threadIdx.y;
    #pragma unroll
    for (int r = 0; r < 4; r++)
        t[ty + 8 * r][tx] = in[ib + (size_t)(s0 + ty + 8 * r) * ldin + d0 + tx];
    __syncthreads();
    #pragma unroll
    for (int r = 0; r < 4; r++)
        out[ob + (size_t)(d0 + ty + 8 * r) * SEQ + s0 + tx] = t[tx][ty + 8 * r];
}

// row softmax of fp32 scores -> fp16 probabilities
__global__ __launch_bounds__(256) void softmax_f16(const float* __restrict__ S,
                                                   fp16* __restrict__ Ph)
{
    const float* row = S + (size_t)blockIdx.x * SEQ;
    const int tid = threadIdx.x;
    __shared__ float red[8];

    float v[8];
    #pragma unroll
    for (int i = 0; i < 8; i++) v[i] = row[tid + i * 256];

    float m = v[0];
    #pragma unroll
    for (int i = 1; i < 8; i++) m = fmaxf(m, v[i]);
    #pragma unroll
    for (int o = 16; o; o >>= 1) m = fmaxf(m, __shfl_xor_sync(0xffffffffu, m, o));
    if ((tid & 31) == 0) red[tid >> 5] = m;
    __syncthreads();
    float mx = red[0];
    #pragma unroll
    for (int w = 1; w < 8; w++) mx = fmaxf(mx, red[w]);
    __syncthreads();

    float s = 0.f;
    #pragma unroll
    for (int i = 0; i < 8; i++) { v[i] = __expf(v[i] - mx); s += v[i]; }
    #pragma unroll
    for (int o = 16; o; o >>= 1) s += __shfl_xor_sync(0xffffffffu, s, o);
    if ((tid & 31) == 0) red[tid >> 5] = s;
    __syncthreads();
    float tot = red[0];
    #pragma unroll
    for (int w = 1; w < 8; w++) tot += red[w];
    const float inv = 1.0f / tot;

    const size_t ro = (size_t)blockIdx.x * SEQ;
    #pragma unroll
    for (int i = 0; i < 8; i++)
        Ph[ro + tid + i * 256] = __float2half(v[i] * inv);
}

// ---------------- launcher ----------------
extern "C" void kernel_launch(void* const* d_in, const int* in_sizes, int n_in,
                              void* d_out, int out_size)
{
    const float* x  = (const float*)d_in[0];
    const float* Wq = (const float*)d_in[1];
    const float* bq = (const float*)d_in[2];
    const float* Wk = (const float*)d_in[3];
    const float* bk = (const float*)d_in[4];
    const float* Wv = (const float*)d_in[5];
    const float* bv = (const float*)d_in[6];
    float* out = (float*)d_out;

    fp16 *x16, *wt, *qkv, *vt, *p;
    float *s, *bias;
    cudaGetSymbolAddress((void**)&x16, g_x16);
    cudaGetSymbolAddress((void**)&wt, g_wt);
    cudaGetSymbolAddress((void**)&qkv, g_qkv);
    cudaGetSymbolAddress((void**)&vt, g_vt);
    cudaGetSymbolAddress((void**)&p, g_p);
    cudaGetSymbolAddress((void**)&s, g_s);
    cudaGetSymbolAddress((void**)&bias, g_bias);

    cudaFuncSetAttribute(gemmw, cudaFuncAttributeMaxDynamicSharedMemorySize, GSMEM);

    const int M = BATCH * SEQ;

    // 1. convert x; transpose W; concat bias
    conv_f16<<<(M * DM / 4 + 255) / 256, 256>>>(x, x16, M * DM / 4);
    transpose_w_f16<<<dim3(DM / 32, DM / 32, 3), dim3(32, 8)>>>(Wq, Wk, Wv, wt);
    concat_bias<<<(3 * DM + 255) / 256, 256>>>(bq, bk, bv, bias);

    // 2. fused QKV projection: [8192, 3072] = x16 @ wt^T + bias
    gemmw<<<dim3(3 * DM / 256, M / 128, 1), 256, GSMEM>>>(
        x16, wt, bias, 1.f,
        nullptr, qkv,
        DM, DM, DM, 3 * DM, 0, 0, 0);

    // 3. V^T
    transpose_f16<<<dim3(DM / 32, SEQ / 32, BATCH), dim3(32, 8)>>>(qkv + 2 * DM, vt, 3 * DM);

    // 4. scores = scale * Q @ K^T (fp32 out)
    gemmw<<<dim3(SEQ / 256, SEQ / 128, BATCH), 256, GSMEM>>>(
        qkv, qkv + DM, nullptr, 0.03125f,
        s, nullptr,
        DM, 3 * DM, 3 * DM, SEQ,
        (size_t)SEQ * 3 * DM, (size_t)SEQ * 3 * DM, (size_t)SEQ * SEQ);

    // 5. softmax -> fp16 probs
    softmax_f16<<<BATCH * SEQ, 256>>>(s, p);

    // 6. out = attn @ V (fp32 out)
    gemmw<<<dim3(DM / 256, SEQ / 128, BATCH), 256, GSMEM>>>(
        p, vt, nullptr, 1.f,
        out, nullptr,
        SEQ, SEQ, SEQ, DM,
        (size_t)SEQ * SEQ, (size_t)DM * SEQ, (size_t)SEQ * DM);
}

// round 11
// speedup vs baseline: 1.1260x; 1.1260x over previous
#include <cuda_runtime.h>
#include <cuda_fp16.h>
#include <stdint.h>

#define BATCH 4
#define SEQ   2048
#define DM    1024
typedef __half fp16;

// ---------------- scratch (__device__ globals; no allocation) ----------------
__device__ fp16 g_x16[(size_t)BATCH*SEQ*DM];      // x single fp16
__device__ fp16 g_wt[(size_t)3*DM*DM];            // W^T single fp16: [3*DM][DM]
__device__ float g_bias[3*DM];
__device__ fp16 g_qkv[(size_t)BATCH*SEQ*3*DM];    // [B*S][3DM]: q | k | v
__device__ fp16 g_vt[(size_t)BATCH*DM*SEQ];       // V^T
__device__ fp16 g_sp[(size_t)BATCH*SEQ*SEQ];      // scores -> probs (fp16, in-place softmax)

// ---------------- helpers ----------------
__device__ __forceinline__ uint32_t s2u(const void* p) {
    uint32_t a;
    asm("{ .reg .u64 t; cvta.to.shared.u64 t, %1; cvt.u32.u64 %0, t; }" : "=r"(a) : "l"(p));
    return a;
}
__device__ __forceinline__ void ldsm4(uint32_t* r, uint32_t addr) {
    asm volatile("ldmatrix.sync.aligned.m8n8.x4.shared.b16 {%0,%1,%2,%3}, [%4];"
                 : "=r"(r[0]), "=r"(r[1]), "=r"(r[2]), "=r"(r[3]) : "r"(addr));
}
__device__ __forceinline__ void mma16816(float* d, const uint32_t* a, uint32_t b0, uint32_t b1) {
    asm volatile(
        "mma.sync.aligned.m16n8k16.row.col.f32.f16.f16.f32 "
        "{%0,%1,%2,%3}, {%4,%5,%6,%7}, {%8,%9}, {%0,%1,%2,%3};"
        : "+f"(d[0]), "+f"(d[1]), "+f"(d[2]), "+f"(d[3])
        : "r"(a[0]), "r"(a[1]), "r"(a[2]), "r"(a[3]), "r"(b0), "r"(b1));
}

// ---------------- HMMA GEMM: C = scale*(A@B^T) [+bias], single fp16 product ----------------
// A [M,K] stride lda, B [N,K] stride ldb, out fp32 Cf OR fp16 Chi (stride ldc).
// CTA 128x128, BK=64, 256 threads (8 warps, warp tile 32x64), 3 stages, 2 CTAs/SM.
// SMSP-partner warps (wid, wid+4) rotate k-step phase by 2.
#define BK      64
#define TILE_B  16384                    // 128 rows * 128B
#define NSTG    3
#define GSMEM   (NSTG * 2 * TILE_B)      // 96 KB

__global__ __launch_bounds__(256, 2) void gemmw(
    const fp16* __restrict__ A, const fp16* __restrict__ B,
    const float* __restrict__ bias, float scale,
    float* __restrict__ Cf, fp16* __restrict__ Chi,
    int K, int lda, int ldb, int ldc,
    size_t sA, size_t sB, size_t sC)
{
    extern __shared__ char smem[];
    const uint32_t sb = s2u(smem);
    const int tid = threadIdx.x;
    const int wid = tid >> 5, lane = tid & 31;
    const int wm = wid & 3, wn = wid >> 2;           // warp grid 4 (m) x 2 (n)
    const int m0 = blockIdx.y * 128, n0 = blockIdx.x * 128;
    const int NC = K / BK;
    const int rot = (wid >> 2) << 1;                 // SMSP partners offset by 2 k-steps

    const fp16* bA = A + (size_t)blockIdx.z * sA + (size_t)m0 * lda;
    const fp16* bB = B + (size_t)blockIdx.z * sB + (size_t)n0 * ldb;

    auto load_chunk = [&](int c) {
        const uint32_t stg = sb + (uint32_t)(c % NSTG) * (2 * TILE_B);
        const int k0 = c * BK;
        #pragma unroll
        for (int i = 0; i < 8; i++) {
            const int t = i >> 2;                       // 0: A, 1: B
            const int sub = tid + (i & 3) * 256;        // 0..1023
            const int row = sub >> 3, col = sub & 7;    // 128 rows x 8 16B-cols
            const int ld = t ? ldb : lda;
            const fp16* src = (t ? bB : bA) + (size_t)row * ld + k0 + col * 8;
            uint32_t off = (uint32_t)(row * 128 + col * 16);
            uint32_t dst = stg + (uint32_t)t * TILE_B + (off ^ ((off >> 3) & 0x70));
            asm volatile("cp.async.cg.shared.global [%0], [%1], 16;" :: "r"(dst), "l"(src) : "memory");
        }
        asm volatile("cp.async.commit_group;" ::: "memory");
    };

    // per-lane ldmatrix addressing (SW128 rows of 128B)
    const int rlane = (lane & 7) + ((lane >> 3) & 1) * 8;
    const uint32_t xlane = (uint32_t)((rlane & 7) * 16);
    const uint32_t kbl = (uint32_t)((lane >> 4) * 16);
    uint32_t aoff[2], boff[4], kx[4];
    #pragma unroll
    for (int mf = 0; mf < 2; mf++) aoff[mf] = (uint32_t)((wm * 32 + mf * 16 + rlane) << 7);
    #pragma unroll
    for (int g = 0; g < 4; g++) boff[g] = (uint32_t)((wn * 64 + g * 16 + rlane) << 7);
    #pragma unroll
    for (int ks = 0; ks < 4; ks++) kx[ks] = ((uint32_t)(ks * 32) + kbl) ^ xlane;

    float acc[2][8][4] = {};

    load_chunk(0);
    if (NC > 1) load_chunk(1);

    for (int c = 0; c < NC; ++c) {
        if (c + 2 < NC) asm volatile("cp.async.wait_group 1;" ::: "memory");
        else            asm volatile("cp.async.wait_group 0;" ::: "memory");
        __syncthreads();                       // chunk c visible; oldest stage free
        if (c + 2 < NC) load_chunk(c + 2);

        const uint32_t stg = sb + (uint32_t)(c % NSTG) * (2 * TILE_B);
        const uint32_t sA_ = stg, sB_ = stg + TILE_B;

        #pragma unroll
        for (int ks = 0; ks < 4; ks++) {
            const uint32_t kk = kx[(ks + rot) & 3];
            uint32_t ah[2][4], bf[8][2];
            ldsm4(ah[0], sA_ + aoff[0] + kk);
            ldsm4(ah[1], sA_ + aoff[1] + kk);
            #pragma unroll
            for (int g = 0; g < 4; g++) {
                uint32_t t[4];
                ldsm4(t, sB_ + boff[g] + kk);
                bf[2*g][0] = t[0]; bf[2*g+1][0] = t[1];
                bf[2*g][1] = t[2]; bf[2*g+1][1] = t[3];
            }
            #pragma unroll
            for (int mf = 0; mf < 2; mf++)
                #pragma unroll
                for (int nf = 0; nf < 8; nf++)
                    mma16816(acc[mf][nf], ah[mf], bf[nf][0], bf[nf][1]);
        }
    }

    // ---------------- epilogue ----------------
    const size_t cb = (size_t)blockIdx.z * sC;
    #pragma unroll
    for (int mf = 0; mf < 2; mf++) {
        #pragma unroll
        for (int nf = 0; nf < 8; nf++) {
            const int m = m0 + wm * 32 + mf * 16 + (lane >> 2);
            const int n = n0 + wn * 64 + nf * 8 + 2 * (lane & 3);
            const float b0 = bias ? bias[n] : 0.f;
            const float b1 = bias ? bias[n + 1] : 0.f;
            float v00 = acc[mf][nf][0] * scale + b0;
            float v01 = acc[mf][nf][1] * scale + b1;
            float v10 = acc[mf][nf][2] * scale + b0;
            float v11 = acc[mf][nf][3] * scale + b1;
            if (Cf) {
                float2 o0 = {v00, v01}, o1 = {v10, v11};
                *reinterpret_cast<float2*>(Cf + cb + (size_t)m * ldc + n)       = o0;
                *reinterpret_cast<float2*>(Cf + cb + (size_t)(m + 8) * ldc + n) = o1;
            } else {
                __half2 ph0 = {__float2half(v00), __float2half(v01)};
                __half2 ph1 = {__float2half(v10), __float2half(v11)};
                *reinterpret_cast<__half2*>(Chi + cb + (size_t)m * ldc + n)       = ph0;
                *reinterpret_cast<__half2*>(Chi + cb + (size_t)(m + 8) * ldc + n) = ph1;
            }
        }
    }
}

// ---------------- aux kernels ----------------
__global__ __launch_bounds__(256) void conv_f16(const float* __restrict__ in,
                                                fp16* __restrict__ o, int n4)
{
    int i = blockIdx.x * 256 + threadIdx.x;
    if (i >= n4) return;
    float4 v = reinterpret_cast<const float4*>(in)[i];
    __align__(8) fp16 h[4];
    h[0] = __float2half(v.x); h[1] = __float2half(v.y);
    h[2] = __float2half(v.z); h[3] = __float2half(v.w);
    reinterpret_cast<uint2*>(o)[i] = *reinterpret_cast<uint2*>(h);
}

__global__ void concat_bias(const float* a, const float* b, const float* c, float* o)
{
    int i = blockIdx.x * 256 + threadIdx.x;
    if (i < DM)            o[i] = a[i];
    else if (i < 2 * DM)   o[i] = b[i - DM];
    else if (i < 3 * DM)   o[i] = c[i - 2 * DM];
}

// W [K=DM, N=DM] fp32 -> wt fp16 [N, K] (transposed), z selects Wq/Wk/Wv
__global__ void transpose_w_f16(const float* __restrict__ Wq, const float* __restrict__ Wk,
                                const float* __restrict__ Wv, fp16* __restrict__ wt)
{
    __shared__ float t[32][33];
    const float* W = blockIdx.z == 0 ? Wq : blockIdx.z == 1 ? Wk : Wv;
    fp16* o = wt + (size_t)blockIdx.z * DM * DM;
    const int n0 = blockIdx.x * 32, k0 = blockIdx.y * 32;
    const int tx = threadIdx.x, ty = threadIdx.y;
    #pragma unroll
    for (int r = 0; r < 4; r++)
        t[ty + 8 * r][tx] = W[(size_t)(k0 + ty + 8 * r) * DM + n0 + tx];
    __syncthreads();
    #pragma unroll
    for (int r = 0; r < 4; r++)
        o[(size_t)(n0 + ty + 8 * r) * DM + k0 + tx] = __float2half(t[tx][ty + 8 * r]);
}

// V slice of [B][SEQ][3*DM] (fp16, stride ldin) -> [B][DM][SEQ] fp16 transpose
__global__ void transpose_f16(const fp16* __restrict__ in, fp16* __restrict__ out, int ldin)
{
    __shared__ fp16 t[32][33];
    const size_t ib = (size_t)blockIdx.z * SEQ * ldin;
    const size_t ob = (size_t)blockIdx.z * DM * SEQ;
    const int s0 = blockIdx.y * 32, d0 = blockIdx.x * 32;
    const int tx = threadIdx.x, ty = threadIdx.y;
    #pragma unroll
    for (int r = 0; r < 4; r++)
        t[ty + 8 * r][tx] = in[ib + (size_t)(s0 + ty + 8 * r) * ldin + d0 + tx];
    __syncthreads();
    #pragma unroll
    for (int r = 0; r < 4; r++)
        out[ob + (size_t)(d0 + ty + 8 * r) * SEQ + s0 + tx] = t[tx][ty + 8 * r];
}

// in-place row softmax on fp16 scores -> fp16 probabilities
__global__ __launch_bounds__(256) void softmax_f16_ip(fp16* __restrict__ SP)
{
    uint32_t* row32 = reinterpret_cast<uint32_t*>(SP + (size_t)blockIdx.x * SEQ);
    const int tid = threadIdx.x;
    __shared__ float red[8];

    float v[8];
    #pragma unroll
    for (int i = 0; i < 4; i++) {
        __half2 h2 = *reinterpret_cast<__half2*>(&row32[tid + i * 256]);
        v[2*i]   = __half2float(__low2half(h2));
        v[2*i+1] = __half2float(__high2half(h2));
    }

    float m = v[0];
    #pragma unroll
    for (int i = 1; i < 8; i++) m = fmaxf(m, v[i]);
    #pragma unroll
    for (int o = 16; o; o >>= 1) m = fmaxf(m, __shfl_xor_sync(0xffffffffu, m, o));
    if ((tid & 31) == 0) red[tid >> 5] = m;
    __syncthreads();
    float mx = red[0];
    #pragma unroll
    for (int w = 1; w < 8; w++) mx = fmaxf(mx, red[w]);
    __syncthreads();

    float s = 0.f;
    #pragma unroll
    for (int i = 0; i < 8; i++) { v[i] = __expf(v[i] - mx); s += v[i]; }
    #pragma unroll
    for (int o = 16; o; o >>= 1) s += __shfl_xor_sync(0xffffffffu, s, o);
    if ((tid & 31) == 0) red[tid >> 5] = s;
    __syncthreads();
    float tot = red[0];
    #pragma unroll
    for (int w = 1; w < 8; w++) tot += red[w];
    const float inv = 1.0f / tot;

    #pragma unroll
    for (int i = 0; i < 4; i++) {
        __half2 h2 = {__float2half(v[2*i] * inv), __float2half(v[2*i+1] * inv)};
        row32[tid + i * 256] = *reinterpret_cast<uint32_t*>(&h2);
    }
}

// ---------------- launcher ----------------
extern "C" void kernel_launch(void* const* d_in, const int* in_sizes, int n_in,
                              void* d_out, int out_size)
{
    const float* x  = (const float*)d_in[0];
    const float* Wq = (const float*)d_in[1];
    const float* bq = (const float*)d_in[2];
    const float* Wk = (const float*)d_in[3];
    const float* bk = (const float*)d_in[4];
    const float* Wv = (const float*)d_in[5];
    const float* bv = (const float*)d_in[6];
    float* out = (float*)d_out;

    fp16 *x16, *wt, *qkv, *vt, *sp;
    float *bias;
    cudaGetSymbolAddress((void**)&x16, g_x16);
    cudaGetSymbolAddress((void**)&wt, g_wt);
    cudaGetSymbolAddress((void**)&qkv, g_qkv);
    cudaGetSymbolAddress((void**)&vt, g_vt);
    cudaGetSymbolAddress((void**)&sp, g_sp);
    cudaGetSymbolAddress((void**)&bias, g_bias);

    cudaFuncSetAttribute(gemmw, cudaFuncAttributeMaxDynamicSharedMemorySize, GSMEM);

    const int M = BATCH * SEQ;

    // 1. convert x; transpose W; concat bias
    conv_f16<<<(M * DM / 4 + 255) / 256, 256>>>(x, x16, M * DM / 4);
    transpose_w_f16<<<dim3(DM / 32, DM / 32, 3), dim3(32, 8)>>>(Wq, Wk, Wv, wt);
    concat_bias<<<(3 * DM + 255) / 256, 256>>>(bq, bk, bv, bias);

    // 2. fused QKV projection: [8192, 3072] = x16 @ wt^T + bias
    gemmw<<<dim3(3 * DM / 128, M / 128, 1), 256, GSMEM>>>(
        x16, wt, bias, 1.f,
        nullptr, qkv,
        DM, DM, DM, 3 * DM, 0, 0, 0);

    // 3. V^T
    transpose_f16<<<dim3(DM / 32, SEQ / 32, BATCH), dim3(32, 8)>>>(qkv + 2 * DM, vt, 3 * DM);

    // 4. scores = scale * Q @ K^T -> fp16
    gemmw<<<dim3(SEQ / 128, SEQ / 128, BATCH), 256, GSMEM>>>(
        qkv, qkv + DM, nullptr, 0.03125f,
        nullptr, sp,
        DM, 3 * DM, 3 * DM, SEQ,
        (size_t)SEQ * 3 * DM, (size_t)SEQ * 3 * DM, (size_t)SEQ * SEQ);

    // 5. in-place softmax on fp16 scores
    softmax_f16_ip<<<BATCH * SEQ, 256>>>(sp);

    // 6. out = attn @ V (fp32 out)
    gemmw<<<dim3(DM / 128, SEQ / 128, BATCH), 256, GSMEM>>>(
        sp, vt, nullptr, 1.f,
        out, nullptr,
        SEQ, SEQ, SEQ, DM,
        (size_t)SEQ * SEQ, (size_t)DM * SEQ, (size_t)SEQ * DM);
}

// round 12
// speedup vs baseline: 1.1728x; 1.0416x over previous
#include <cuda_runtime.h>
#include <cuda_fp16.h>
#include <stdint.h>

#define BATCH 4
#define SEQ   2048
#define DM    1024
typedef __half fp16;

// ---------------- scratch (__device__ globals; no allocation) ----------------
__device__ fp16 g_x16[(size_t)BATCH*SEQ*DM];      // x single fp16
__device__ fp16 g_wt[(size_t)3*DM*DM];            // W^T single fp16: [3*DM][DM]
__device__ float g_bias[3*DM];
__device__ fp16 g_qkv[(size_t)BATCH*SEQ*3*DM];    // [B*S][3DM]: q | k | v
__device__ fp16 g_vt[(size_t)BATCH*DM*SEQ];       // V^T
__device__ fp16 g_sp[(size_t)BATCH*SEQ*SEQ];      // scores -> probs (fp16, in-place softmax)

// ---------------- helpers ----------------
__device__ __forceinline__ uint32_t s2u(const void* p) {
    uint32_t a;
    asm("{ .reg .u64 t; cvta.to.shared.u64 t, %1; cvt.u32.u64 %0, t; }" : "=r"(a) : "l"(p));
    return a;
}
__device__ __forceinline__ void ldsm4(uint32_t* r, uint32_t addr) {
    asm volatile("ldmatrix.sync.aligned.m8n8.x4.shared.b16 {%0,%1,%2,%3}, [%4];"
                 : "=r"(r[0]), "=r"(r[1]), "=r"(r[2]), "=r"(r[3]) : "r"(addr));
}
__device__ __forceinline__ void mma16816(float* d, const uint32_t* a, uint32_t b0, uint32_t b1) {
    asm volatile(
        "mma.sync.aligned.m16n8k16.row.col.f32.f16.f16.f32 "
        "{%0,%1,%2,%3}, {%4,%5,%6,%7}, {%8,%9}, {%0,%1,%2,%3};"
        : "+f"(d[0]), "+f"(d[1]), "+f"(d[2]), "+f"(d[3])
        : "r"(a[0]), "r"(a[1]), "r"(a[2]), "r"(a[3]), "r"(b0), "r"(b1));
}

// ---------------- HMMA GEMM: C = scale*(A@B^T) [+bias], single fp16 product ----------------
// A [M,K] stride lda, B [N,K] stride ldb, out fp32 Cf OR fp16 Chi (stride ldc).
// CTA 128x128, BK=64, 256 threads (8 warps, warp tile 32x64), 3 stages, 2 CTAs/SM.
// (R9 shape exactly — rotation removed after R11 measured it as a ~5% regression.)
#define BK      64
#define TILE_B  16384                    // 128 rows * 128B
#define NSTG    3
#define GSMEM   (NSTG * 2 * TILE_B)      // 96 KB

__global__ __launch_bounds__(256, 2) void gemmw(
    const fp16* __restrict__ A, const fp16* __restrict__ B,
    const float* __restrict__ bias, float scale,
    float* __restrict__ Cf, fp16* __restrict__ Chi,
    int K, int lda, int ldb, int ldc,
    size_t sA, size_t sB, size_t sC)
{
    extern __shared__ char smem[];
    const uint32_t sb = s2u(smem);
    const int tid = threadIdx.x;
    const int wid = tid >> 5, lane = tid & 31;
    const int wm = wid & 3, wn = wid >> 2;           // warp grid 4 (m) x 2 (n)
    const int m0 = blockIdx.y * 128, n0 = blockIdx.x * 128;
    const int NC = K / BK;

    const fp16* bA = A + (size_t)blockIdx.z * sA + (size_t)m0 * lda;
    const fp16* bB = B + (size_t)blockIdx.z * sB + (size_t)n0 * ldb;

    auto load_chunk = [&](int c) {
        const uint32_t stg = sb + (uint32_t)(c % NSTG) * (2 * TILE_B);
        const int k0 = c * BK;
        #pragma unroll
        for (int i = 0; i < 8; i++) {
            const int t = i >> 2;                       // 0: A, 1: B
            const int sub = tid + (i & 3) * 256;        // 0..1023
            const int row = sub >> 3, col = sub & 7;    // 128 rows x 8 16B-cols
            const int ld = t ? ldb : lda;
            const fp16* src = (t ? bB : bA) + (size_t)row * ld + k0 + col * 8;
            uint32_t off = (uint32_t)(row * 128 + col * 16);
            uint32_t dst = stg + (uint32_t)t * TILE_B + (off ^ ((off >> 3) & 0x70));
            asm volatile("cp.async.cg.shared.global [%0], [%1], 16;" :: "r"(dst), "l"(src) : "memory");
        }
        asm volatile("cp.async.commit_group;" ::: "memory");
    };

    // per-lane ldmatrix addressing (SW128 rows of 128B)
    const int rlane = (lane & 7) + ((lane >> 3) & 1) * 8;
    const uint32_t xlane = (uint32_t)((rlane & 7) * 16);
    const uint32_t kbl = (uint32_t)((lane >> 4) * 16);
    uint32_t aoff[2], boff[4], kx[4];
    #pragma unroll
    for (int mf = 0; mf < 2; mf++) aoff[mf] = (uint32_t)((wm * 32 + mf * 16 + rlane) << 7);
    #pragma unroll
    for (int g = 0; g < 4; g++) boff[g] = (uint32_t)((wn * 64 + g * 16 + rlane) << 7);
    #pragma unroll
    for (int ks = 0; ks < 4; ks++) kx[ks] = ((uint32_t)(ks * 32) + kbl) ^ xlane;

    float acc[2][8][4] = {};

    load_chunk(0);
    if (NC > 1) load_chunk(1);

    for (int c = 0; c < NC; ++c) {
        if (c + 2 < NC) asm volatile("cp.async.wait_group 1;" ::: "memory");
        else            asm volatile("cp.async.wait_group 0;" ::: "memory");
        __syncthreads();                       // chunk c visible; oldest stage free
        if (c + 2 < NC) load_chunk(c + 2);

        const uint32_t stg = sb + (uint32_t)(c % NSTG) * (2 * TILE_B);
        const uint32_t sA_ = stg, sB_ = stg + TILE_B;

        #pragma unroll
        for (int ks = 0; ks < 4; ks++) {
            uint32_t ah[2][4], bf[8][2];
            ldsm4(ah[0], sA_ + aoff[0] + kx[ks]);
            ldsm4(ah[1], sA_ + aoff[1] + kx[ks]);
            #pragma unroll
            for (int g = 0; g < 4; g++) {
                uint32_t t[4];
                ldsm4(t, sB_ + boff[g] + kx[ks]);
                bf[2*g][0] = t[0]; bf[2*g+1][0] = t[1];
                bf[2*g][1] = t[2]; bf[2*g+1][1] = t[3];
            }
            #pragma unroll
            for (int mf = 0; mf < 2; mf++)
                #pragma unroll
                for (int nf = 0; nf < 8; nf++)
                    mma16816(acc[mf][nf], ah[mf], bf[nf][0], bf[nf][1]);
        }
    }

    // ---------------- epilogue ----------------
    const size_t cb = (size_t)blockIdx.z * sC;
    #pragma unroll
    for (int mf = 0; mf < 2; mf++) {
        #pragma unroll
        for (int nf = 0; nf < 8; nf++) {
            const int m = m0 + wm * 32 + mf * 16 + (lane >> 2);
            const int n = n0 + wn * 64 + nf * 8 + 2 * (lane & 3);
            const float b0 = bias ? bias[n] : 0.f;
            const float b1 = bias ? bias[n + 1] : 0.f;
            float v00 = acc[mf][nf][0] * scale + b0;
            float v01 = acc[mf][nf][1] * scale + b1;
            float v10 = acc[mf][nf][2] * scale + b0;
            float v11 = acc[mf][nf][3] * scale + b1;
            if (Cf) {
                float2 o0 = {v00, v01}, o1 = {v10, v11};
                *reinterpret_cast<float2*>(Cf + cb + (size_t)m * ldc + n)       = o0;
                *reinterpret_cast<float2*>(Cf + cb + (size_t)(m + 8) * ldc + n) = o1;
            } else {
                __half2 ph0 = {__float2half(v00), __float2half(v01)};
                __half2 ph1 = {__float2half(v10), __float2half(v11)};
                *reinterpret_cast<__half2*>(Chi + cb + (size_t)m * ldc + n)       = ph0;
                *reinterpret_cast<__half2*>(Chi + cb + (size_t)(m + 8) * ldc + n) = ph1;
            }
        }
    }
}

// ---------------- aux kernels ----------------
__global__ __launch_bounds__(256) void conv_f16(const float* __restrict__ in,
                                                fp16* __restrict__ o, int n4)
{
    int i = blockIdx.x * 256 + threadIdx.x;
    if (i >= n4) return;
    float4 v = reinterpret_cast<const float4*>(in)[i];
    __align__(8) fp16 h[4];
    h[0] = __float2half(v.x); h[1] = __float2half(v.y);
    h[2] = __float2half(v.z); h[3] = __float2half(v.w);
    reinterpret_cast<uint2*>(o)[i] = *reinterpret_cast<uint2*>(h);
}

__global__ void concat_bias(const float* a, const float* b, const float* c, float* o)
{
    int i = blockIdx.x * 256 + threadIdx.x;
    if (i < DM)            o[i] = a[i];
    else if (i < 2 * DM)   o[i] = b[i - DM];
    else if (i < 3 * DM)   o[i] = c[i - 2 * DM];
}

// W [K=DM, N=DM] fp32 -> wt fp16 [N, K] (transposed), z selects Wq/Wk/Wv
__global__ void transpose_w_f16(const float* __restrict__ Wq, const float* __restrict__ Wk,
                                const float* __restrict__ Wv, fp16* __restrict__ wt)
{
    __shared__ float t[32][33];
    const float* W = blockIdx.z == 0 ? Wq : blockIdx.z == 1 ? Wk : Wv;
    fp16* o = wt + (size_t)blockIdx.z * DM * DM;
    const int n0 = blockIdx.x * 32, k0 = blockIdx.y * 32;
    const int tx = threadIdx.x, ty = threadIdx.y;
    #pragma unroll
    for (int r = 0; r < 4; r++)
        t[ty + 8 * r][tx] = W[(size_t)(k0 + ty + 8 * r) * DM + n0 + tx];
    __syncthreads();
    #pragma unroll
    for (int r = 0; r < 4; r++)
        o[(size_t)(n0 + ty + 8 * r) * DM + k0 + tx] = __float2half(t[tx][ty + 8 * r]);
}

// V slice of [B][SEQ][3*DM] (fp16, stride ldin) -> [B][DM][SEQ] fp16 transpose
__global__ void transpose_f16(const fp16* __restrict__ in, fp16* __restrict__ out, int ldin)
{
    __shared__ fp16 t[32][33];
    const size_t ib = (size_t)blockIdx.z * SEQ * ldin;
    const size_t ob = (size_t)blockIdx.z * DM * SEQ;
    const int s0 = blockIdx.y * 32, d0 = blockIdx.x * 32;
    const int tx = threadIdx.x, ty = threadIdx.y;
    #pragma unroll
    for (int r = 0; r < 4; r++)
        t[ty + 8 * r][tx] = in[ib + (size_t)(s0 + ty + 8 * r) * ldin + d0 + tx];
    __syncthreads();
    #pragma unroll
    for (int r = 0; r < 4; r++)
        out[ob + (size_t)(d0 + ty + 8 * r) * SEQ + s0 + tx] = t[tx][ty + 8 * r];
}

// in-place row softmax on fp16 scores -> fp16 probabilities
__global__ __launch_bounds__(256) void softmax_f16_ip(fp16* __restrict__ SP)
{
    uint32_t* row32 = reinterpret_cast<uint32_t*>(SP + (size_t)blockIdx.x * SEQ);
    const int tid = threadIdx.x;
    __shared__ float red[8];

    float v[8];
    #pragma unroll
    for (int i = 0; i < 4; i++) {
        __half2 h2 = *reinterpret_cast<__half2*>(&row32[tid + i * 256]);
        v[2*i]   = __half2float(__low2half(h2));
        v[2*i+1] = __half2float(__high2half(h2));
    }

    float m = v[0];
    #pragma unroll
    for (int i = 1; i < 8; i++) m = fmaxf(m, v[i]);
    #pragma unroll
    for (int o = 16; o; o >>= 1) m = fmaxf(m, __shfl_xor_sync(0xffffffffu, m, o));
    if ((tid & 31) == 0) red[tid >> 5] = m;
    __syncthreads();
    float mx = red[0];
    #pragma unroll
    for (int w = 1; w < 8; w++) mx = fmaxf(mx, red[w]);
    __syncthreads();

    float s = 0.f;
    #pragma unroll
    for (int i = 0; i < 8; i++) { v[i] = __expf(v[i] - mx); s += v[i]; }
    #pragma unroll
    for (int o = 16; o; o >>= 1) s += __shfl_xor_sync(0xffffffffu, s, o);
    if ((tid & 31) == 0) red[tid >> 5] = s;
    __syncthreads();
    float tot = red[0];
    #pragma unroll
    for (int w = 1; w < 8; w++) tot += red[w];
    const float inv = 1.0f / tot;

    #pragma unroll
    for (int i = 0; i < 4; i++) {
        __half2 h2 = {__float2half(v[2*i] * inv), __float2half(v[2*i+1] * inv)};
        row32[tid + i * 256] = *reinterpret_cast<uint32_t*>(&h2);
    }
}

// ---------------- launcher ----------------
extern "C" void kernel_launch(void* const* d_in, const int* in_sizes, int n_in,
                              void* d_out, int out_size)
{
    const float* x  = (const float*)d_in[0];
    const float* Wq = (const float*)d_in[1];
    const float* bq = (const float*)d_in[2];
    const float* Wk = (const float*)d_in[3];
    const float* bk = (const float*)d_in[4];
    const float* Wv = (const float*)d_in[5];
    const float* bv = (const float*)d_in[6];
    float* out = (float*)d_out;

    fp16 *x16, *wt, *qkv, *vt, *sp;
    float *bias;
    cudaGetSymbolAddress((void**)&x16, g_x16);
    cudaGetSymbolAddress((void**)&wt, g_wt);
    cudaGetSymbolAddress((void**)&qkv, g_qkv);
    cudaGetSymbolAddress((void**)&vt, g_vt);
    cudaGetSymbolAddress((void**)&sp, g_sp);
    cudaGetSymbolAddress((void**)&bias, g_bias);

    cudaFuncSetAttribute(gemmw, cudaFuncAttributeMaxDynamicSharedMemorySize, GSMEM);

    const int M = BATCH * SEQ;

    // 1. convert x; transpose W; concat bias
    conv_f16<<<(M * DM / 4 + 255) / 256, 256>>>(x, x16, M * DM / 4);
    transpose_w_f16<<<dim3(DM / 32, DM / 32, 3), dim3(32, 8)>>>(Wq, Wk, Wv, wt);
    concat_bias<<<(3 * DM + 255) / 256, 256>>>(bq, bk, bv, bias);

    // 2. fused QKV projection: [8192, 3072] = x16 @ wt^T + bias
    gemmw<<<dim3(3 * DM / 128, M / 128, 1), 256, GSMEM>>>(
        x16, wt, bias, 1.f,
        nullptr, qkv,
        DM, DM, DM, 3 * DM, 0, 0, 0);

    // 3. V^T
    transpose_f16<<<dim3(DM / 32, SEQ / 32, BATCH), dim3(32, 8)>>>(qkv + 2 * DM, vt, 3 * DM);

    // 4. scores = scale * Q @ K^T -> fp16
    gemmw<<<dim3(SEQ / 128, SEQ / 128, BATCH), 256, GSMEM>>>(
        qkv, qkv + DM, nullptr, 0.03125f,
        nullptr, sp,
        DM, 3 * DM, 3 * DM, SEQ,
        (size_t)SEQ * 3 * DM, (size_t)SEQ * 3 * DM, (size_t)SEQ * SEQ);

    // 5. in-place softmax on fp16 scores
    softmax_f16_ip<<<BATCH * SEQ, 256>>>(sp);

    // 6. out = attn @ V (fp32 out)
    gemmw<<<dim3(DM / 128, SEQ / 128, BATCH), 256, GSMEM>>>(
        sp, vt, nullptr, 1.f,
        out, nullptr,
        SEQ, SEQ, SEQ, DM,
        (size_t)SEQ * SEQ, (size_t)DM * SEQ, (size_t)SEQ * DM);
}